// round 7
// baseline (speedup 1.0000x reference)
#include <cuda_runtime.h>

// Problem constants
#define BB 32
#define FF 64
#define LL 8192
#define KK 8
#define TT 128          // output steps per scan chunk
#define WW 128          // warm-up steps (validated rounds 2-6: rel_err ~8.7e-8)
#define NCH (LL / TT)   // 64 chunks -> 2048 scan blocks
#define TILE 32         // steps buffered in smem before coalesced write-out
#define TPAD 36         // row stride: conflict-free STS.128 / LDS.128 / logits
#define XS_N (WW + TT + KK)   // 264

#define NSCAN (BB * NCH)      // 2048 scan blocks
#define NCONV 1024            // conv blocks: 2 (b,f) rows each (one per warp)
#define NBLK  (NSCAN + NCONV) // 3072

#define X_SCALE 20.0f
#define THR 0.25f
#define BETA 15.0f

// Heterogeneous kernel:
//  - scan role: conv + LIF recurrence + z/s/logits (I NOT staged/stored)
//  - conv role: causal conv only, writes I fully coalesced (no recurrence)
// Roles interleaved mod 3 over blockIdx.x so every wave mixes latency-bound
// scan blocks with throughput-bound conv blocks.
__global__ __launch_bounds__(64, 16) void snn_hetero_kernel(
    const float* __restrict__ x,
    const float* __restrict__ conv_w,
    const float* __restrict__ raw_tau,
    float* __restrict__ out)
{
    __shared__ float xs[XS_N];
    __shared__ float tZ[FF * TPAD];
    __shared__ float pm[TILE * 2];

    const int bx = blockIdx.x;
    const int f = threadIdx.x;
    const bool is_conv = ((bx % 3) == 2);

    float* const outI = out;
    float* const outZ = out + (size_t)BB * FF * LL;
    float* const outS = out + (size_t)2 * BB * FF * LL;
    float* const logits = out + (size_t)3 * BB * FF * LL;

    if (is_conv) {
        // ---------------- conv role: I[row, :] for 2 rows, 1 per warp -------
        const int rowid = 2 * (bx / 3) + (f >> 5);   // 0..2047
        const int cb = rowid >> 6;                   // batch
        const int cf = rowid & 63;                   // filter
        const int lane = f & 31;

        float w[KK];
        float nrm = 0.0f;
#pragma unroll
        for (int k = 0; k < KK; k++) {
            w[k] = conv_w[cf * KK + k];
            nrm += w[k] * w[k];
        }
        nrm = fmaxf(sqrtf(nrm), 1e-8f);
#pragma unroll
        for (int k = 0; k < KK; k++) w[k] = w[k] / nrm;

        const float4* x4 = (const float4*)(x + cb * LL);
        float4* o4 = (float4*)(outI + (size_t)rowid * LL);
        const float4 z4c = make_float4(0.f, 0.f, 0.f, 0.f);

        for (int i = 0; i < 64; i++) {
            const int t4 = i * 32 + lane;
            const float4 a2 = x4[t4];
            const float4 a0 = (t4 >= 2) ? x4[t4 - 2] : z4c;
            const float4 a1 = (t4 >= 1) ? x4[t4 - 1] : z4c;
            // X[m] = x[4*t4 - 7 + m], m = 0..10
            float X[11];
            X[0] = a0.y; X[1] = a0.z; X[2] = a0.w;
            X[3] = a1.x; X[4] = a1.y; X[5] = a1.z; X[6] = a1.w;
            X[7] = a2.x; X[8] = a2.y; X[9] = a2.z; X[10] = a2.w;
            float4 r;
            float s0 = 0.f, s1 = 0.f, s2 = 0.f, s3 = 0.f;
#pragma unroll
            for (int k = 0; k < KK; k++) {
                s0 = fmaf(w[k], X[k], s0);
                s1 = fmaf(w[k], X[k + 1], s1);
                s2 = fmaf(w[k], X[k + 2], s2);
                s3 = fmaf(w[k], X[k + 3], s3);
            }
            r.x = X_SCALE * s0; r.y = X_SCALE * s1;
            r.z = X_SCALE * s2; r.w = X_SCALE * s3;
            o4[t4] = r;
        }
        return;
    }

    // ---------------- scan role ----------------------------------------
    const int sid = (bx / 3) * 2 + (bx % 3);   // 0..2047
    const int b = sid >> 6;                    // batch
    const int c = sid & 63;                    // chunk
    const int t0 = c * TT;
    const int tstart = (c == 0) ? 0 : (t0 - WW);
    const int nwarm = t0 - tstart;             // 0 or WW

    float w[KK];
    float nrm = 0.0f;
#pragma unroll
    for (int k = 0; k < KK; k++) {
        w[k] = conv_w[f * KK + k];
        nrm += w[k] * w[k];
    }
    nrm = fmaxf(sqrtf(nrm), 1e-8f);
#pragma unroll
    for (int k = 0; k < KK; k++) w[k] = w[k] / nrm;

    const float rt = raw_tau[f];
    const float sp = fmaxf(rt, 0.0f) + log1pf(expf(-fabsf(rt)));
    const float alpha = expf(-1.0f / (sp + 1e-4f));
    const float oma = 1.0f - alpha;

    // Stage pre-scaled x window, zero-padded left. xs[i] = 20*x[b, tstart-7+i]
    const float* xb = x + b * LL;
    const int base = tstart - (KK - 1);
    const int total = nwarm + TT + (KK - 1);
    for (int i = f; i < total; i += FF) {
        const int g = base + i;
        xs[i] = (g >= 0) ? (X_SCALE * xb[g]) : 0.0f;
    }
    __syncthreads();

    // 8-register circular window: win[(p+k)&7] == xs[p+k]
    float win[8];
#pragma unroll
    for (int i = 0; i < 8; i++) win[i] = xs[i];

    float v = 0.0f;

    // warm-up: recurrence only
    for (int p = 0; p < nwarm; p += 8) {
#pragma unroll
        for (int u = 0; u < 8; u++) {
            float I = 0.0f;
#pragma unroll
            for (int k = 0; k < KK; k++) I = fmaf(w[k], win[(u + k) & 7], I);
            const float vpre = fmaf(oma, I, alpha * v);
            v = (vpre >= THR) ? 0.0f : vpre;
            win[u] = xs[p + u + 8];
        }
    }

    const int g2 = f >> 5;        // warp id
    const int cc = f & 31;        // time column

    for (int jb = 0; jb < TT; jb += TILE) {
#pragma unroll
        for (int q = 0; q < TILE; q += 8) {
            float Za[8];
#pragma unroll
            for (int u = 0; u < 8; u++) {
                float I = 0.0f;
#pragma unroll
                for (int k = 0; k < KK; k++) I = fmaf(w[k], win[(u + k) & 7], I);
                const float vpre = fmaf(oma, I, alpha * v);
                Za[u] = fmaf(BETA, vpre, -BETA * THR);
                v = (vpre >= THR) ? 0.0f : vpre;
                win[u] = xs[nwarm + jb + q + u + 8];
            }
            const int off = f * TPAD + q;
            *(float4*)&tZ[off]     = make_float4(Za[0], Za[1], Za[2], Za[3]);
            *(float4*)&tZ[off + 4] = make_float4(Za[4], Za[5], Za[6], Za[7]);
        }
        __syncthreads();

        const int colbase = t0 + jb;

        // Coalesced z & s write-out (s = z >= 0)
#pragma unroll
        for (int p2 = 0; p2 < 8; p2++) {
            const int idx = p2 * 256 + f * 4;
            const int row = idx >> 5;
            const int col = idx & 31;
            const size_t g = (size_t)(b * FF + row) * LL + colbase + col;
            const float4 z4 = *(const float4*)&tZ[row * TPAD + col];
            float4 s4;
            s4.x = (z4.x >= 0.0f) ? 1.0f : 0.0f;
            s4.y = (z4.y >= 0.0f) ? 1.0f : 0.0f;
            s4.z = (z4.z >= 0.0f) ? 1.0f : 0.0f;
            s4.w = (z4.w >= 0.0f) ? 1.0f : 0.0f;
            *(float4*)&outZ[g] = z4;
            *(float4*)&outS[g] = s4;
        }

        // Logits: warp g2 reduces its 32 filters for column cc.
        {
            float m = -3.4e38f;
#pragma unroll
            for (int ff2 = 0; ff2 < 32; ff2++)
                m = fmaxf(m, tZ[(g2 * 32 + ff2) * TPAD + cc]);
            pm[cc * 2 + g2] = m;
        }
        __syncthreads();

        if (f < TILE) {
            logits[b * LL + colbase + f] = fmaxf(pm[f * 2], pm[f * 2 + 1]);
        }
    }
}

extern "C" void kernel_launch(void* const* d_in, const int* in_sizes, int n_in,
                              void* d_out, int out_size)
{
    const float* x       = (const float*)d_in[0];
    const float* conv_w  = (const float*)d_in[1];
    const float* raw_tau = (const float*)d_in[2];
    float* out = (float*)d_out;

    snn_hetero_kernel<<<NBLK, FF>>>(x, conv_w, raw_tau, out);
}